// round 7
// baseline (speedup 1.0000x reference)
#include <cuda_runtime.h>
#include <cuda_fp16.h>

// Problem constants
#define B_DIM 2048
#define IN_DIM 8192
#define O_DIM 4096
#define K_DIM 64

#define BS 8          // b-slice per CTA
#define NCTA (B_DIM / BS)   // 256 CTAs
#define NTHR 512      // 16 warps

// Packed (idx<<16 | fp16(w)) table, o-major: g_pk[o*64 + k]. 1 MB.
__device__ unsigned int g_pk[O_DIM * K_DIM];

// ---------------------------------------------------------------------------
// Kernel 0: pack idx+w into one word each.
// ---------------------------------------------------------------------------
__global__ __launch_bounds__(256) void pack_kernel(const int* __restrict__ indices,
                                                   const float* __restrict__ weight) {
    int t = blockIdx.x * blockDim.x + threadIdx.x;
    if (t < O_DIM * K_DIM) {
        unsigned int hw = __half_as_ushort(__float2half(weight[t]));
        g_pk[t] = ((unsigned int)indices[t] << 16) | hw;
    }
}

// ---------------------------------------------------------------------------
// Kernel 1: smem-resident gather.
// R4/R5 ncu: two occupancy configs both pinned at 103.6us = exact L2 sector
// roof for the 1.07GB gather stream -> L2-BW bound, occupancy irrelevant.
// R7: gather served from SMEM instead of L2. CTA owns 8 consecutive b's;
// loads x rows (contiguous -> no transpose pass at all) as fp16 slice
// sl[8192][8] (128KB). Sweep all (o,k) pairs; thread owns whole o's ->
// register accumulation, coalesced out stores (lanes = consecutive o).
// Crossbar: 1.07GB @ 33TB/s aggregate, ~1.9x random-row bank conflicts.
// ---------------------------------------------------------------------------
extern __shared__ __half sl[];  // [IN_DIM][BS] = 128 KB

__global__ __launch_bounds__(NTHR) void gather2_kernel(const float* __restrict__ x,
                                                       const float* __restrict__ bias,
                                                       float* __restrict__ out) {
    const int tid = threadIdx.x;
    const int b0 = blockIdx.x * BS;

    // Load + convert slice: coalesced float4 reads over IN per b, scattered STS.16.
#pragma unroll
    for (int bb = 0; bb < BS; bb++) {
        const float4* __restrict__ xrow = (const float4*)(x + (size_t)(b0 + bb) * IN_DIM);
        for (int i4 = tid; i4 < IN_DIM / 4; i4 += NTHR) {
            const float4 v = xrow[i4];
            sl[(i4 * 4 + 0) * BS + bb] = __float2half(v.x);
            sl[(i4 * 4 + 1) * BS + bb] = __float2half(v.y);
            sl[(i4 * 4 + 2) * BS + bb] = __float2half(v.z);
            sl[(i4 * 4 + 3) * BS + bb] = __float2half(v.w);
        }
    }
    __syncthreads();

    // Sweep: thread t handles o = t, t+NTHR, ... (8 o's). Lanes within a warp
    // hold consecutive o -> coalesced output stores.
    for (int o = tid; o < O_DIM; o += NTHR) {
        float acc[BS];
#pragma unroll
        for (int q = 0; q < BS; q++) acc[q] = 0.f;

        const uint4* __restrict__ p = (const uint4*)(g_pk + o * K_DIM);  // 256B/o, aligned

#pragma unroll 4
        for (int kk = 0; kk < K_DIM / 4; kk++) {
            const uint4 u = p[kk];
            const unsigned int uw[4] = {u.x, u.y, u.z, u.w};
#pragma unroll
            for (int j = 0; j < 4; j++) {
                const unsigned int e = uw[j];
                const float w = __half2float(__ushort_as_half((unsigned short)(e & 0xFFFFu)));
                const int row = (int)(e >> 16);
                const uint4 v = *(const uint4*)(sl + row * BS);  // LDS.128: 8 halves
                const __half2* h = (const __half2*)&v;
#pragma unroll
                for (int q = 0; q < 4; q++) {
                    const float2 f = __half22float2(h[q]);
                    acc[2 * q + 0] += f.x * w;
                    acc[2 * q + 1] += f.y * w;
                }
            }
        }

        const float bv = bias[o];
#pragma unroll
        for (int bb = 0; bb < BS; bb++) {
            out[(size_t)(b0 + bb) * O_DIM + o] = acc[bb] + bv;  // coalesced across lanes
        }
    }
}

// ---------------------------------------------------------------------------
// Launch
// ---------------------------------------------------------------------------
extern "C" void kernel_launch(void* const* d_in, const int* in_sizes, int n_in,
                              void* d_out, int out_size) {
    (void)in_sizes; (void)n_in; (void)out_size;
    const float* x = (const float*)d_in[0];
    const int* indices = (const int*)d_in[1];
    const float* weight = (const float*)d_in[2];
    const float* bias = (const float*)d_in[3];
    float* out = (float*)d_out;

    const int smem_bytes = IN_DIM * BS * sizeof(__half);  // 128 KB
    static int configured = 0;
    if (!configured) {
        cudaFuncSetAttribute(gather2_kernel, cudaFuncAttributeMaxDynamicSharedMemorySize,
                             smem_bytes);
        configured = 1;
    }

    pack_kernel<<<(O_DIM * K_DIM + 255) / 256, 256>>>(indices, weight);
    gather2_kernel<<<NCTA, NTHR, smem_bytes>>>(x, bias, out);
}